// round 12
// baseline (speedup 1.0000x reference)
#include <cuda_runtime.h>
#include <stdint.h>

#define NT 512
#define NTA 256
#define CHUNKS 8
#define MAXB 128
#define MAXCH 8
#define CAPC 256
#define HSZ 2048
#define HMASK (HSZ-1)
#define SORTN 2048
#define CCAP  2040
#define NEG_INF_F (-3.4028234663852886e38f)
#define PAD_IDX 0x7FFFFFFF
#define TH0 3.0f
#define L2E 1.44269504f
#define BIAS8 11.54156036f   /* 8 * log2(e) */
#define PREW 128

// ---- global scratch (allocation-free) ----
__device__ float g_candv[MAXB * MAXCH * CAPC];
__device__ int   g_candi[MAXB * MAXCH * CAPC];
__device__ int   g_ccnt[MAXB * MAXCH];
__device__ float g_ps[MAXB * MAXCH];

__device__ __forceinline__ uint32_t rotl32(uint32_t x, int r) {
    return (x << r) | (x >> (32 - r));
}

// JAX threefry2x32, key=(0,42), partitionable random_bits: bits = word0 ^ word1
__device__ __forceinline__ float gumbel_for(uint32_t idx) {
    uint32_t x0 = 0u, x1 = idx;
    const uint32_t k0 = 0u, k1 = 42u;
    const uint32_t k2 = 0x1BD11BDAu ^ k0 ^ k1;
    x0 += k0; x1 += k1;
#define TFR(r) { x0 += x1; x1 = rotl32(x1, (r)); x1 ^= x0; }
    TFR(13) TFR(15) TFR(26) TFR(6)  x0 += k1; x1 += k2 + 1u;
    TFR(17) TFR(29) TFR(16) TFR(24) x0 += k2; x1 += k0 + 2u;
    TFR(13) TFR(15) TFR(26) TFR(6)  x0 += k0; x1 += k1 + 3u;
    TFR(17) TFR(29) TFR(16) TFR(24) x0 += k1; x1 += k2 + 4u;
    TFR(13) TFR(15) TFR(26) TFR(6)  x0 += k2; x1 += k0 + 5u;
#undef TFR
    uint32_t bits = x0 ^ x1;
    float f = __uint_as_float((bits >> 9) | 0x3f800000u) - 1.0f;
    float u = fmaxf(1e-10f, f + 1e-10f);
    return -logf(-logf(u));
}

__device__ __forceinline__ void hash_insert(int* hkey, unsigned* hval, int tok,
                                            unsigned v, bool is_flag) {
    int h = tok & HMASK;
    while (true) {
        int prev = atomicCAS(&hkey[h], -1, tok);
        if (prev == -1 || prev == tok) {
            if (is_flag) atomicOr(&hval[h], v);
            else         atomicAdd(&hval[h], v);
            return;
        }
        h = (h + 1) & HMASK;
    }
}

__device__ __forceinline__ bool hash_find(const int* hkey, const unsigned* hval,
                                          int tok, unsigned* out) {
    int h = tok & HMASK;
    while (true) {
        int kk = hkey[h];
        if (kk == tok) { *out = hval[h]; return true; }
        if (kk == -1) { *out = 0u; return false; }
        h = (h + 1) & HMASK;
    }
}

__device__ __forceinline__ float process_val(float x, unsigned info, bool penalize,
                                             float rep, float freq, float pres,
                                             float teff) {
    unsigned cnt   = info & 0xFFFFu;
    bool in_out    = cnt != 0u;
    bool in_prompt = (info & (1u << 16)) != 0u;
    bool is_stop   = (info & (1u << 17)) != 0u;
    float v = x;
    if (penalize && is_stop) v = NEG_INF_F;
    if (in_prompt || in_out)
        v = (v > 0.0f) ? __fdiv_rn(v, rep) : __fmul_rn(v, rep);
    v = __fsub_rn(v, __fmul_rn(freq, (float)cnt));
    v = __fsub_rn(v, in_out ? pres : 0.0f);
    v = __fdiv_rn(v, teff);
    return v;
}

__device__ __forceinline__ float ex2a(float t) {
    float r;
    asm("ex2.approx.ftz.f32 %0, %1;" : "=f"(r) : "f"(t));
    return r;
}

// Register-resident bitonic sort of 256 elements in threads 0..255 (R9-proven).
// MODE 1: (val asc, idx desc)   MODE 2: (val asc, idx asc)
template <int MODE>
__device__ void reg_bitonic_256(int t, float* skey, int* sidx) {
    float v = 0.0f; int x = PAD_IDX;
    if (t < 256) { v = skey[t]; x = sidx[t]; }
    #pragma unroll
    for (int k = 2; k <= 256; k <<= 1) {
        #pragma unroll
        for (int j = k >> 1; j > 0; j >>= 1) {
            float pv; int px;
            if (j < 32) {
                pv = __shfl_xor_sync(0xFFFFFFFFu, v, j);
                px = __shfl_xor_sync(0xFFFFFFFFu, x, j);
            } else {
                __syncthreads();
                if (t < 256) { skey[t] = v; sidx[t] = x; }
                __syncthreads();
                if (t < 256) { pv = skey[t ^ j]; px = sidx[t ^ j]; }
                else         { pv = v; px = x; }
            }
            if (t < 256) {
                bool iGt = (MODE == 1) ? ((v > pv) || (v == pv && x < px))
                                       : ((v > pv) || (v == pv && x > px));
                bool keepMax = (((t & j) == 0) != ((t & k) == 0));
                if (keepMax ? !iGt : iGt) { v = pv; x = px; }
            }
        }
    }
    __syncthreads();
    if (t < 256) { skey[t] = v; sidx[t] = x; }
    __syncthreads();
}

// Generic LDS bitonic for NP > 256 (rare fallback path)
__device__ void lds_bitonic(int tid, float* skey, int* sidx, int NP, int mode) {
    #pragma unroll 1
    for (int ksz = 2; ksz <= NP; ksz <<= 1) {
        #pragma unroll 1
        for (int j = ksz >> 1; j > 0; j >>= 1) {
            for (int i = tid; i < NP; i += NT) {
                int ixj = i ^ j;
                if (ixj > i) {
                    float a = skey[i], c2 = skey[ixj];
                    int ai = sidx[i], ci = sidx[ixj];
                    bool gt = (a > c2) || (a == c2 && ((mode == 1) ? (ai < ci) : (ai > ci)));
                    if (((i & ksz) == 0) ? gt : !gt) {
                        skey[i] = c2; skey[ixj] = a;
                        sidx[i] = ci; sidx[ixj] = ai;
                    }
                }
            }
            __syncthreads();
        }
    }
}

// ==================== kernel 1: streaming scan ====================
__global__ void __launch_bounds__(NTA, 4)
scan_kernel(const float* __restrict__ logits, int V, int C) {
    const int b = blockIdx.x / C;
    const int c = blockIdx.x % C;
    const int tid = threadIdx.x;
    __shared__ int s_cnt;
    __shared__ float rS[NTA / 32];
    if (tid == 0) s_cnt = 0;
    __syncthreads();

    const float* row = logits + (size_t)b * V;
    const int chunk = (((V + C - 1) / C) + 3) & ~3;
    const int s0 = min(c * chunk, V);
    const int s1 = min(s0 + chunk, V);
    const int n4 = (s1 - s0) >> 2;
    const float4* p4 = (const float4*)(row + s0);

    float* slice_v = g_candv + (b * C + c) * CAPC;
    int*   slice_i = g_candi + (b * C + c) * CAPC;

    float a0s = 0.0f, a1s = 0.0f, a2s = 0.0f, a3s = 0.0f;

    int i = tid;
    for (; i + NTA < n4; i += 2 * NTA) {
        float4 a = p4[i];
        float4 q = p4[i + NTA];
        a0s += ex2a(__fmaf_rn(a.x, L2E, -BIAS8));
        a1s += ex2a(__fmaf_rn(a.y, L2E, -BIAS8));
        a2s += ex2a(__fmaf_rn(a.z, L2E, -BIAS8));
        a3s += ex2a(__fmaf_rn(a.w, L2E, -BIAS8));
        a0s += ex2a(__fmaf_rn(q.x, L2E, -BIAS8));
        a1s += ex2a(__fmaf_rn(q.y, L2E, -BIAS8));
        a2s += ex2a(__fmaf_rn(q.z, L2E, -BIAS8));
        a3s += ex2a(__fmaf_rn(q.w, L2E, -BIAS8));
        float mA = fmaxf(fmaxf(a.x, a.y), fmaxf(a.z, a.w));
        float mQ = fmaxf(fmaxf(q.x, q.y), fmaxf(q.z, q.w));
        if (mA > TH0) {
            int base = s0 + (i << 2);
            float xs[4] = {a.x, a.y, a.z, a.w};
            #pragma unroll
            for (int l = 0; l < 4; ++l)
                if (xs[l] > TH0) {
                    int p = atomicAdd(&s_cnt, 1);
                    if (p < CAPC) { slice_v[p] = xs[l]; slice_i[p] = base + l; }
                }
        }
        if (mQ > TH0) {
            int base = s0 + ((i + NTA) << 2);
            float xs[4] = {q.x, q.y, q.z, q.w};
            #pragma unroll
            for (int l = 0; l < 4; ++l)
                if (xs[l] > TH0) {
                    int p = atomicAdd(&s_cnt, 1);
                    if (p < CAPC) { slice_v[p] = xs[l]; slice_i[p] = base + l; }
                }
        }
    }
    for (; i < n4; i += NTA) {
        float4 a = p4[i];
        a0s += ex2a(__fmaf_rn(a.x, L2E, -BIAS8));
        a1s += ex2a(__fmaf_rn(a.y, L2E, -BIAS8));
        a2s += ex2a(__fmaf_rn(a.z, L2E, -BIAS8));
        a3s += ex2a(__fmaf_rn(a.w, L2E, -BIAS8));
        float mA = fmaxf(fmaxf(a.x, a.y), fmaxf(a.z, a.w));
        if (mA > TH0) {
            int base = s0 + (i << 2);
            float xs[4] = {a.x, a.y, a.z, a.w};
            #pragma unroll
            for (int l = 0; l < 4; ++l)
                if (xs[l] > TH0) {
                    int p = atomicAdd(&s_cnt, 1);
                    if (p < CAPC) { slice_v[p] = xs[l]; slice_i[p] = base + l; }
                }
        }
    }
    for (int j = s0 + (n4 << 2) + tid; j < s1; j += NTA) {
        float x = row[j];
        a0s += ex2a(__fmaf_rn(x, L2E, -BIAS8));
        if (x > TH0) {
            int p = atomicAdd(&s_cnt, 1);
            if (p < CAPC) { slice_v[p] = x; slice_i[p] = j; }
        }
    }

    float S = (a0s + a1s) + (a2s + a3s);
    #pragma unroll
    for (int off = 16; off; off >>= 1)
        S += __shfl_down_sync(0xFFFFFFFFu, S, off);
    if ((tid & 31) == 0) rS[tid >> 5] = S;
    __syncthreads();
    if (tid == 0) {
        float SS = rS[0];
        for (int w = 1; w < NTA / 32; ++w) SS += rS[w];
        g_ps[b * C + c] = SS;
        g_ccnt[b * C + c] = s_cnt;
    }
}

// ==================== kernel 2: finish (two phases per row) ====================
__global__ void __launch_bounds__(NT, 1)
finish_kernel(const float* __restrict__ logits,
              const float* __restrict__ temperature,
              const float* __restrict__ presence,
              const float* __restrict__ frequency,
              const float* __restrict__ repetition,
              const float* __restrict__ top_p,
              const int* __restrict__ prompt_ids,
              const int* __restrict__ output_ids,
              const int* __restrict__ output_lens,
              const int* __restrict__ stop_ids,
              const int* __restrict__ min_tokens,
              const int* __restrict__ top_k,
              float* __restrict__ out,
              int B, int V, int P, int O, int S, int T, int C)
{
    const int b     = blockIdx.x;
    const int phase = blockIdx.y;
    const int tid   = threadIdx.x;

    __shared__ int      hkey[HSZ];
    __shared__ unsigned hval[HSZ];
    __shared__ float    skey[SORTN];
    __shared__ int      sidx[SORTN];
    __shared__ float    pre_e[PREW], pre_g[PREW];
    __shared__ float    sh_ps[MAXCH];
    __shared__ int      sh_cc[MAXCH];
    __shared__ int      s_cnt, s_unt;
    __shared__ float    s_logS;

    const bool fastShape = (P == 1024) && (O <= 256) && (S <= 256) && (C == MAXCH);

    // ---- EARLY global loads: issue everything before smem work ----
    if (tid < C) { sh_ps[tid] = g_ps[b * C + tid]; sh_cc[tid] = g_ccnt[b * C + tid]; }
    if (tid == 0) s_unt = 0;

    const float* sv = g_candv + (size_t)b * C * CAPC;
    const int*   si = g_candi + (size_t)b * C * CAPC;

    // phase-1 batched register loads
    int4 pr = make_int4(0, 0, 0, 0);
    int  oid = 0, sidr = 0, olen_l = 0;
    float rv8[8]; int ri8[8];
    // phase-0 batched register loads
    float rv4[4]; int ri4[4];

    if (phase == 1) {
        olen_l = output_lens[b];
        if (fastShape) {
            if (tid < 256) {
                pr = ((const int4*)(prompt_ids + (size_t)b * P))[tid];
                if (tid < O) oid = output_ids[(size_t)b * O + tid];
                if (tid < S) sidr = stop_ids[(size_t)b * S + tid];
            } else {
                int t2 = tid - 256;
                #pragma unroll
                for (int c = 0; c < MAXCH; ++c) {
                    rv8[c] = sv[c * CAPC + t2];
                    ri8[c] = si[c * CAPC + t2];
                }
            }
        }
        // hash init (all threads)
        for (int i = tid; i < HSZ; i += NT) { hkey[i] = -1; hval[i] = 0u; }
    } else {
        // phase 0: 512 threads x 4 chunks each
        int t2 = tid & 255;
        int ch0 = (tid >> 8) * 4;
        #pragma unroll
        for (int c = 0; c < 4; ++c) {
            rv4[c] = sv[(ch0 + c) * CAPC + t2];
            ri4[c] = si[(ch0 + c) * CAPC + t2];
        }
        if (tid == 0) {
            float Ssum = 0.0f;
            #pragma unroll
            for (int c = 0; c < MAXCH; ++c) Ssum += g_ps[b * C + c];
            s_logS = logf(Ssum) + 8.0f;
        }
    }
    __syncthreads();

    // ---- local candidate accounting from sh_cc ----
    int cnt = 0; bool overflow0 = false;
    int pref[MAXCH + 1];
    {
        pref[0] = 0;
        #pragma unroll
        for (int c = 0; c < MAXCH; ++c) {
            int cc = sh_cc[c];
            if (cc > CAPC) { overflow0 = true; cc = CAPC; }
            cnt += cc;
            pref[c + 1] = cnt;
        }
        if (cnt > CCAP) { overflow0 = true; cnt = CCAP; }
    }
    const bool small = !overflow0 && (cnt <= 256);
    const int base_off = small ? (256 - cnt) : 0;

    if (phase == 1) {
        // warps 0-7: hash inserts from registers || warps 8-15: store gathered
        if (tid < 256) {
            if (fastShape) {
                hash_insert(hkey, hval, pr.x, 1u << 16, true);
                hash_insert(hkey, hval, pr.y, 1u << 16, true);
                hash_insert(hkey, hval, pr.z, 1u << 16, true);
                hash_insert(hkey, hval, pr.w, 1u << 16, true);
                if (tid < O && tid < olen_l) hash_insert(hkey, hval, oid, 1u, false);
                if (tid < S) hash_insert(hkey, hval, sidr, 1u << 17, true);
            } else {
                for (int i = tid; i < P; i += 256)
                    hash_insert(hkey, hval, prompt_ids[(size_t)b * P + i], 1u << 16, true);
                for (int i = tid; i < O; i += 256)
                    if (i < olen_l)
                        hash_insert(hkey, hval, output_ids[(size_t)b * O + i], 1u, false);
                for (int i = tid; i < S; i += 256)
                    hash_insert(hkey, hval, stop_ids[(size_t)b * S + i], 1u << 17, true);
            }
        } else if (!overflow0) {
            int t2 = tid - 256;
            if (small)
                for (int j = t2; j < 256 - cnt; j += 256) { skey[j] = -INFINITY; sidx[j] = PAD_IDX; }
            if (fastShape) {
                #pragma unroll
                for (int c = 0; c < MAXCH; ++c) {
                    int cc = pref[c + 1] - pref[c];
                    if (t2 < cc) {
                        skey[base_off + pref[c] + t2] = rv8[c];
                        sidx[base_off + pref[c] + t2] = ri8[c];
                    }
                }
            } else {
                for (int c = 0; c < C; ++c) {
                    int cc = pref[c + 1] - pref[c];
                    for (int j = t2; j < cc; j += 256) {
                        skey[base_off + pref[c] + j] = sv[c * CAPC + j];
                        sidx[base_off + pref[c] + j] = si[c * CAPC + j];
                    }
                }
            }
        }
        __syncthreads();
    } else {
        // phase 0: store gathered registers
        if (!overflow0) {
            int t2 = tid & 255;
            int ch0 = (tid >> 8) * 4;
            if (small)
                for (int j = tid; j < 256 - cnt; j += NT) { skey[j] = -INFINITY; sidx[j] = PAD_IDX; }
            #pragma unroll
            for (int c = 0; c < 4; ++c) {
                int cg = ch0 + c;
                int cc = pref[cg + 1] - pref[cg];
                if (t2 < cc) {
                    skey[base_off + pref[cg] + t2] = rv4[c];
                    sidx[base_off + pref[cg] + t2] = ri4[c];
                }
            }
        }
        __syncthreads();
    }

    // -------- untouched-count check (phase 1 only) --------
    bool need_fallback;
    if (phase == 1) {
        if (!overflow0) {
            for (int j = tid; j < cnt; j += NT) {
                unsigned info;
                if (!hash_find(hkey, hval, sidx[base_off + j], &info)) atomicAdd(&s_unt, 1);
            }
        }
        __syncthreads();
        need_fallback = overflow0 || (s_unt < 68);
    } else {
        need_fallback = overflow0 || (cnt < 32);
    }
    __syncthreads();

    // -------- rare fallback: rescan with adaptive threshold --------
    if (need_fallback) {
        const float* row = logits + (size_t)b * V;
        float tcur = overflow0 ? (TH0 + 1.0f) : (TH0 - 1.5f);
        for (int attempt = 0; attempt < 8; ++attempt) {
            if (tid == 0) { s_cnt = 0; s_unt = 0; }
            __syncthreads();
            const int nv4 = V >> 2;
            const float4* row4 = (const float4*)row;
            for (int i = tid; i < nv4; i += NT) {
                float4 v4 = row4[i];
                float xs[4] = {v4.x, v4.y, v4.z, v4.w};
                #pragma unroll
                for (int l = 0; l < 4; ++l) {
                    float x = xs[l];
                    if (x > tcur) {
                        int p = atomicAdd(&s_cnt, 1);
                        if (p < CCAP) { skey[p] = x; sidx[p] = (i << 2) + l; }
                    }
                }
            }
            for (int i = (nv4 << 2) + tid; i < V; i += NT) {
                float x = row[i];
                if (x > tcur) {
                    int p = atomicAdd(&s_cnt, 1);
                    if (p < CCAP) { skey[p] = x; sidx[p] = i; }
                }
            }
            __syncthreads();
            cnt = s_cnt;
            bool overflow = cnt > CCAP;
            if (overflow) cnt = CCAP;
            if (phase == 1) {
                for (int j = tid; j < cnt; j += NT) {
                    unsigned info;
                    if (!hash_find(hkey, hval, sidx[j], &info)) atomicAdd(&s_unt, 1);
                }
            }
            __syncthreads();
            int unt = s_unt;
            __syncthreads();
            if (overflow) { tcur += 1.0f; continue; }
            if (phase == 1) { if (unt >= 68) break; }
            else            { if (cnt >= 32) break; }
            tcur -= 1.5f;
        }
        int NPf = 256;
        while (NPf < cnt) NPf <<= 1;
        float rvt[4]; int rit[4];
        #pragma unroll
        for (int r = 0; r < 4; ++r) {
            int j = tid + r * NT;
            if (j < cnt) { rvt[r] = skey[j]; rit[r] = sidx[j]; }
        }
        __syncthreads();
        for (int j = tid; j < NPf; j += NT) { skey[j] = -INFINITY; sidx[j] = PAD_IDX; }
        __syncthreads();
        #pragma unroll
        for (int r = 0; r < 4; ++r) {
            int j = tid + r * NT;
            if (j < cnt) { skey[NPf - cnt + j] = rvt[r]; sidx[NPf - cnt + j] = rit[r]; }
        }
        __syncthreads();
    } else if (!small) {
        int NPf = 256;
        while (NPf < cnt) NPf <<= 1;
        float rvt[4]; int rit[4];
        #pragma unroll
        for (int r = 0; r < 4; ++r) {
            int j = tid + r * NT;
            if (j < cnt) { rvt[r] = skey[j]; rit[r] = sidx[j]; }
        }
        __syncthreads();
        for (int j = tid; j < NPf; j += NT) { skey[j] = -INFINITY; sidx[j] = PAD_IDX; }
        __syncthreads();
        #pragma unroll
        for (int r = 0; r < 4; ++r) {
            int j = tid + r * NT;
            if (j < cnt) { skey[NPf - cnt + j] = rvt[r]; sidx[NPf - cnt + j] = rit[r]; }
        }
        __syncthreads();
    }

    int NP = 256;
    while (NP < cnt) NP <<= 1;
    const bool use_reg = (NP == 256);

    if (phase == 0) {
        if (use_reg) reg_bitonic_256<1>(tid, skey, sidx);
        else         lds_bitonic(tid, skey, sidx, NP, 1);

        const float slogS = s_logS;
        if (tid < T) {
            float v = skey[NP - 1 - tid];
            int   ix = sidx[NP - 1 - tid];
            out[B + (size_t)b * T + tid] = __fsub_rn(v, slogS);
            out[B + (size_t)B * T + (size_t)b * T + tid] = (float)ix;
        }
        return;
    }

    // ================= sampling phase =================
    const float temp  = temperature[b];
    const float presv = presence[b];
    const float freqv = frequency[b];
    const float repv  = repetition[b];
    const float toppv = top_p[b];
    const int   mint  = min_tokens[b];
    const bool  penalize = olen_l < mint;
    const float teff = (temp < 1e-5f) ? 1.0f : temp;

    for (int j = tid; j < NP; j += NT) {
        int ix = sidx[j];
        if (ix < V) {
            unsigned info;
            hash_find(hkey, hval, ix, &info);
            skey[j] = process_val(skey[j], info, penalize, repv, freqv, presv, teff);
        }
    }
    __syncthreads();

    if (use_reg) reg_bitonic_256<2>(tid, skey, sidx);
    else         lds_bitonic(tid, skey, sidx, NP, 2);

    int W2 = (NP < PREW) ? NP : PREW;
    int wbase = NP - W2;
    float vmax = skey[NP - 1];
    if (tid < W2) {
        int p = wbase + tid;
        int ix = sidx[p];
        if (ix < V) {
            pre_e[tid] = expf(skey[p] - vmax);
            pre_g[tid] = skey[p] + gumbel_for((uint32_t)b * (uint32_t)V + (uint32_t)ix);
        } else {
            pre_e[tid] = 0.0f;
            pre_g[tid] = -INFINITY;
        }
    }
    __syncthreads();

    if (tid == 0) {
        int k = top_k[b];
        if (k < 1) k = 1;
        if (k > V) k = V;
        if (k > cnt) k = cnt;

        float kth = skey[NP - k];
        int p0 = NP - k;
        while (p0 > 0 && skey[p0 - 1] == kth) --p0;

        int q = NP - 1;
        while (q > 0 && skey[q - 1] == vmax) --q;
        int greedy = sidx[q];

        float S2 = 0.0f;
        for (int p = p0; p < NP; ++p) {
            int w = p - wbase;
            S2 += (w >= 0) ? pre_e[w] : expf(skey[p] - vmax);
        }
        float invS2 = 1.0f / S2;

        float thr = 1.0f - toppv;
        float cum = 0.0f;
        float best = -INFINITY;
        int bestIdx = PAD_IDX;
        for (int p = p0; p < NP; ++p) {
            int w = p - wbase;
            float e = (w >= 0) ? pre_e[w] : expf(skey[p] - vmax);
            cum += e / S2;
            bool drop = (cum <= thr) && (p != NP - 1);
            if (!drop) {
                float score;
                if (w >= 0) score = pre_g[w];
                else {
                    int ix = sidx[p];
                    score = (ix < V) ? skey[p] + gumbel_for((uint32_t)b * (uint32_t)V + (uint32_t)ix)
                                     : -INFINITY;
                }
                if (score > best || (score == best && sidx[p] < bestIdx)) {
                    best = score; bestIdx = sidx[p];
                }
            }
        }
        (void)invS2;
        int sampled = (temp < 1e-5f) ? greedy : bestIdx;
        out[b] = (float)sampled;
    }
}

extern "C" void kernel_launch(void* const* d_in, const int* in_sizes, int n_in,
                              void* d_out, int out_size) {
    const float* logits      = (const float*)d_in[0];
    const float* temperature = (const float*)d_in[1];
    const float* presence    = (const float*)d_in[2];
    const float* frequency   = (const float*)d_in[3];
    const float* repetition  = (const float*)d_in[4];
    const float* topp        = (const float*)d_in[5];
    const int*   prompt      = (const int*)d_in[6];
    const int*   outids      = (const int*)d_in[7];
    const int*   outlens     = (const int*)d_in[8];
    const int*   stops       = (const int*)d_in[9];
    const int*   mintok      = (const int*)d_in[10];
    const int*   topk        = (const int*)d_in[11];

    int B = in_sizes[1];
    int V = in_sizes[0] / B;
    int P = in_sizes[6] / B;
    int O = in_sizes[7] / B;
    int S = in_sizes[9] / B;
    int T = (out_size / B - 1) / 2;
    int C = CHUNKS;

    scan_kernel<<<B * C, NTA>>>(logits, V, C);
    dim3 gridF(B, 2);
    finish_kernel<<<gridF, NT>>>(logits, temperature, presence, frequency, repetition,
                                 topp, prompt, outids, outlens, stops, mintok, topk,
                                 (float*)d_out, B, V, P, O, S, T, C);
}

// round 13
// speedup vs baseline: 1.2936x; 1.2936x over previous
#include <cuda_runtime.h>
#include <stdint.h>

#define NTT 1024
#define NSCAN 768
#define HSZ 2048
#define HMASK (HSZ-1)
#define SORTN 2048
#define CCAP  2040
#define NEG_INF_F (-3.4028234663852886e38f)
#define PAD_IDX 0x7FFFFFFF
#define TH0 3.0f
#define L2E 1.44269504f
#define BIAS8 11.54156036f   /* 8 * log2(e) */
#define PREW 128

__device__ __forceinline__ uint32_t rotl32(uint32_t x, int r) {
    return (x << r) | (x >> (32 - r));
}

// JAX threefry2x32, key=(0,42), partitionable random_bits: bits = word0 ^ word1
__device__ __forceinline__ float gumbel_for(uint32_t idx) {
    uint32_t x0 = 0u, x1 = idx;
    const uint32_t k0 = 0u, k1 = 42u;
    const uint32_t k2 = 0x1BD11BDAu ^ k0 ^ k1;
    x0 += k0; x1 += k1;
#define TFR(r) { x0 += x1; x1 = rotl32(x1, (r)); x1 ^= x0; }
    TFR(13) TFR(15) TFR(26) TFR(6)  x0 += k1; x1 += k2 + 1u;
    TFR(17) TFR(29) TFR(16) TFR(24) x0 += k2; x1 += k0 + 2u;
    TFR(13) TFR(15) TFR(26) TFR(6)  x0 += k0; x1 += k1 + 3u;
    TFR(17) TFR(29) TFR(16) TFR(24) x0 += k1; x1 += k2 + 4u;
    TFR(13) TFR(15) TFR(26) TFR(6)  x0 += k2; x1 += k0 + 5u;
#undef TFR
    uint32_t bits = x0 ^ x1;
    float f = __uint_as_float((bits >> 9) | 0x3f800000u) - 1.0f;
    float u = fmaxf(1e-10f, f + 1e-10f);
    return -logf(-logf(u));
}

__device__ __forceinline__ void hash_insert(int* hkey, unsigned* hval, int tok,
                                            unsigned v, bool is_flag) {
    int h = tok & HMASK;
    while (true) {
        int prev = atomicCAS(&hkey[h], -1, tok);
        if (prev == -1 || prev == tok) {
            if (is_flag) atomicOr(&hval[h], v);
            else         atomicAdd(&hval[h], v);
            return;
        }
        h = (h + 1) & HMASK;
    }
}

__device__ __forceinline__ bool hash_find(const int* hkey, const unsigned* hval,
                                          int tok, unsigned* out) {
    int h = tok & HMASK;
    while (true) {
        int kk = hkey[h];
        if (kk == tok) { *out = hval[h]; return true; }
        if (kk == -1) { *out = 0u; return false; }
        h = (h + 1) & HMASK;
    }
}

__device__ __forceinline__ float process_val(float x, unsigned info, bool penalize,
                                             float rep, float freq, float pres,
                                             float teff) {
    unsigned cnt   = info & 0xFFFFu;
    bool in_out    = cnt != 0u;
    bool in_prompt = (info & (1u << 16)) != 0u;
    bool is_stop   = (info & (1u << 17)) != 0u;
    float v = x;
    if (penalize && is_stop) v = NEG_INF_F;
    if (in_prompt || in_out)
        v = (v > 0.0f) ? __fdiv_rn(v, rep) : __fmul_rn(v, rep);
    v = __fsub_rn(v, __fmul_rn(freq, (float)cnt));
    v = __fsub_rn(v, in_out ? pres : 0.0f);
    v = __fdiv_rn(v, teff);
    return v;
}

__device__ __forceinline__ float ex2a(float t) {
    float r;
    asm("ex2.approx.ftz.f32 %0, %1;" : "=f"(r) : "f"(t));
    return r;
}

// Register-resident bitonic sort of 256 elements in threads 0..255.
// ALL threads of the block must call (unconditional barriers inside).
// MODE 1: (val asc, idx desc)   MODE 2: (val asc, idx asc)
template <int MODE>
__device__ void reg_bitonic_256(int t, float* skey, int* sidx) {
    float v = 0.0f; int x = PAD_IDX;
    if (t < 256) { v = skey[t]; x = sidx[t]; }
    #pragma unroll
    for (int k = 2; k <= 256; k <<= 1) {
        #pragma unroll
        for (int j = k >> 1; j > 0; j >>= 1) {
            float pv; int px;
            if (j < 32) {
                pv = __shfl_xor_sync(0xFFFFFFFFu, v, j);
                px = __shfl_xor_sync(0xFFFFFFFFu, x, j);
            } else {
                __syncthreads();
                if (t < 256) { skey[t] = v; sidx[t] = x; }
                __syncthreads();
                if (t < 256) { pv = skey[t ^ j]; px = sidx[t ^ j]; }
                else         { pv = v; px = x; }
            }
            if (t < 256) {
                bool iGt = (MODE == 1) ? ((v > pv) || (v == pv && x < px))
                                       : ((v > pv) || (v == pv && x > px));
                bool keepMax = (((t & j) == 0) != ((t & k) == 0));
                if (keepMax ? !iGt : iGt) { v = pv; x = px; }
            }
        }
    }
    __syncthreads();
    if (t < 256) { skey[t] = v; sidx[t] = x; }
    __syncthreads();
}

// Generic LDS bitonic for NP > 256 (rare path)
__device__ void lds_bitonic(int tid, float* skey, int* sidx, int NP, int mode) {
    #pragma unroll 1
    for (int ksz = 2; ksz <= NP; ksz <<= 1) {
        #pragma unroll 1
        for (int j = ksz >> 1; j > 0; j >>= 1) {
            for (int i = tid; i < NP; i += NTT) {
                int ixj = i ^ j;
                if (ixj > i) {
                    float a = skey[i], c2 = skey[ixj];
                    int ai = sidx[i], ci = sidx[ixj];
                    bool gt = (a > c2) || (a == c2 && ((mode == 1) ? (ai < ci) : (ai > ci)));
                    if (((i & ksz) == 0) ? gt : !gt) {
                        skey[i] = c2; skey[ixj] = a;
                        sidx[i] = ci; sidx[ixj] = ai;
                    }
                }
            }
            __syncthreads();
        }
    }
}

// ==================== fused kernel: one CTA per row ====================
__global__ void __launch_bounds__(NTT, 1)
fused_kernel(const float* __restrict__ logits,
             const float* __restrict__ temperature,
             const float* __restrict__ presence,
             const float* __restrict__ frequency,
             const float* __restrict__ repetition,
             const float* __restrict__ top_p,
             const int* __restrict__ prompt_ids,
             const int* __restrict__ output_ids,
             const int* __restrict__ output_lens,
             const int* __restrict__ stop_ids,
             const int* __restrict__ min_tokens,
             const int* __restrict__ top_k,
             float* __restrict__ out,
             int B, int V, int P, int O, int S, int T)
{
    __shared__ int      hkey[HSZ];
    __shared__ unsigned hval[HSZ];
    __shared__ float    skey[SORTN];
    __shared__ int      sidx[SORTN];
    __shared__ float    pre_e[PREW], pre_g[PREW];
    __shared__ float    redS[NSCAN / 32];
    __shared__ int      s_cnt, s_unt;
    __shared__ float    s_logS;

    const int b   = blockIdx.x;
    const int tid = threadIdx.x;
    const float* row = logits + (size_t)b * V;

    // ---- init hash + counters (all threads) ----
    for (int i = tid; i < HSZ; i += NTT) { hkey[i] = -1; hval[i] = 0u; }
    if (tid == 0) { s_cnt = 0; s_unt = 0; }
    __syncthreads();

    const int olen_l = output_lens[b];

    if (tid < NSCAN) {
        // ======== scanner warps: stream row, sum exp(x-8), collect x>TH0 ========
        const int n4 = V >> 2;
        const float4* p4 = (const float4*)row;
        float a0s = 0.0f, a1s = 0.0f, a2s = 0.0f, a3s = 0.0f;

        int i = tid;
        for (; i + NSCAN < n4; i += 2 * NSCAN) {
            float4 a = p4[i];
            float4 q = p4[i + NSCAN];
            a0s += ex2a(__fmaf_rn(a.x, L2E, -BIAS8));
            a1s += ex2a(__fmaf_rn(a.y, L2E, -BIAS8));
            a2s += ex2a(__fmaf_rn(a.z, L2E, -BIAS8));
            a3s += ex2a(__fmaf_rn(a.w, L2E, -BIAS8));
            a0s += ex2a(__fmaf_rn(q.x, L2E, -BIAS8));
            a1s += ex2a(__fmaf_rn(q.y, L2E, -BIAS8));
            a2s += ex2a(__fmaf_rn(q.z, L2E, -BIAS8));
            a3s += ex2a(__fmaf_rn(q.w, L2E, -BIAS8));
            float mA = fmaxf(fmaxf(a.x, a.y), fmaxf(a.z, a.w));
            float mQ = fmaxf(fmaxf(q.x, q.y), fmaxf(q.z, q.w));
            if (mA > TH0) {
                int base = i << 2;
                float xs[4] = {a.x, a.y, a.z, a.w};
                #pragma unroll
                for (int l = 0; l < 4; ++l)
                    if (xs[l] > TH0) {
                        int p = atomicAdd(&s_cnt, 1);
                        if (p < CCAP) { skey[p] = xs[l]; sidx[p] = base + l; }
                    }
            }
            if (mQ > TH0) {
                int base = (i + NSCAN) << 2;
                float xs[4] = {q.x, q.y, q.z, q.w};
                #pragma unroll
                for (int l = 0; l < 4; ++l)
                    if (xs[l] > TH0) {
                        int p = atomicAdd(&s_cnt, 1);
                        if (p < CCAP) { skey[p] = xs[l]; sidx[p] = base + l; }
                    }
            }
        }
        for (; i < n4; i += NSCAN) {
            float4 a = p4[i];
            a0s += ex2a(__fmaf_rn(a.x, L2E, -BIAS8));
            a1s += ex2a(__fmaf_rn(a.y, L2E, -BIAS8));
            a2s += ex2a(__fmaf_rn(a.z, L2E, -BIAS8));
            a3s += ex2a(__fmaf_rn(a.w, L2E, -BIAS8));
            float mA = fmaxf(fmaxf(a.x, a.y), fmaxf(a.z, a.w));
            if (mA > TH0) {
                int base = i << 2;
                float xs[4] = {a.x, a.y, a.z, a.w};
                #pragma unroll
                for (int l = 0; l < 4; ++l)
                    if (xs[l] > TH0) {
                        int p = atomicAdd(&s_cnt, 1);
                        if (p < CCAP) { skey[p] = xs[l]; sidx[p] = base + l; }
                    }
            }
        }
        for (int j = (n4 << 2) + tid; j < V; j += NSCAN) {
            float x = row[j];
            a0s += ex2a(__fmaf_rn(x, L2E, -BIAS8));
            if (x > TH0) {
                int p = atomicAdd(&s_cnt, 1);
                if (p < CCAP) { skey[p] = x; sidx[p] = j; }
            }
        }

        float Sl = (a0s + a1s) + (a2s + a3s);
        #pragma unroll
        for (int off = 16; off; off >>= 1)
            Sl += __shfl_down_sync(0xFFFFFFFFu, Sl, off);
        if ((tid & 31) == 0) redS[tid >> 5] = Sl;
    } else {
        // ======== hash warps: build touched-token table concurrently ========
        int t2 = tid - NSCAN;  // 0..255
        if (P == 1024) {
            int4 pr = ((const int4*)(prompt_ids + (size_t)b * P))[t2];
            hash_insert(hkey, hval, pr.x, 1u << 16, true);
            hash_insert(hkey, hval, pr.y, 1u << 16, true);
            hash_insert(hkey, hval, pr.z, 1u << 16, true);
            hash_insert(hkey, hval, pr.w, 1u << 16, true);
        } else {
            for (int i = t2; i < P; i += 256)
                hash_insert(hkey, hval, prompt_ids[(size_t)b * P + i], 1u << 16, true);
        }
        for (int i = t2; i < O; i += 256)
            if (i < olen_l)
                hash_insert(hkey, hval, output_ids[(size_t)b * O + i], 1u, false);
        for (int i = t2; i < S; i += 256)
            hash_insert(hkey, hval, stop_ids[(size_t)b * S + i], 1u << 17, true);
    }
    __syncthreads();

    if (tid == 0) {
        float Ssum = 0.0f;
        for (int w = 0; w < NSCAN / 32; ++w) Ssum += redS[w];
        s_logS = logf(Ssum) + 8.0f;
    }

    // ---- untouched-count check ----
    int cnt = s_cnt;
    bool overflow0 = cnt > CCAP;
    if (overflow0) cnt = CCAP;
    if (!overflow0) {
        for (int j = tid; j < cnt; j += NTT) {
            unsigned info;
            if (!hash_find(hkey, hval, sidx[j], &info)) atomicAdd(&s_unt, 1);
        }
    }
    __syncthreads();
    bool need_fallback = overflow0 || (s_unt < 68);
    __syncthreads();

    // ---- rare fallback: rescan (row is L2-resident) with adaptive threshold ----
    if (need_fallback) {
        float tcur = overflow0 ? (TH0 + 1.0f) : (TH0 - 1.5f);
        for (int attempt = 0; attempt < 8; ++attempt) {
            if (tid == 0) { s_cnt = 0; s_unt = 0; }
            __syncthreads();
            const int nv4 = V >> 2;
            const float4* row4 = (const float4*)row;
            for (int i = tid; i < nv4; i += NTT) {
                float4 v4 = row4[i];
                float xs[4] = {v4.x, v4.y, v4.z, v4.w};
                #pragma unroll
                for (int l = 0; l < 4; ++l) {
                    float x = xs[l];
                    if (x > tcur) {
                        int p = atomicAdd(&s_cnt, 1);
                        if (p < CCAP) { skey[p] = x; sidx[p] = (i << 2) + l; }
                    }
                }
            }
            for (int i = (nv4 << 2) + tid; i < V; i += NTT) {
                float x = row[i];
                if (x > tcur) {
                    int p = atomicAdd(&s_cnt, 1);
                    if (p < CCAP) { skey[p] = x; sidx[p] = i; }
                }
            }
            __syncthreads();
            cnt = s_cnt;
            bool overflow = cnt > CCAP;
            if (overflow) cnt = CCAP;
            for (int j = tid; j < cnt; j += NTT) {
                unsigned info;
                if (!hash_find(hkey, hval, sidx[j], &info)) atomicAdd(&s_unt, 1);
            }
            __syncthreads();
            int unt = s_unt;
            __syncthreads();
            if (overflow) { tcur += 1.0f; continue; }
            if (unt >= 68) break;
            tcur -= 1.5f;
        }
    }

    const float slogS = s_logS;

    // ---- relocate candidates [0,cnt) to tail of pow2 region ----
    int NP = 256;
    while (NP < cnt) NP <<= 1;
    const bool use_reg = (NP == 256);

    float rv[2]; int ri[2];
    #pragma unroll
    for (int r = 0; r < 2; ++r) {
        int j = tid + r * NTT;
        if (j < cnt) { rv[r] = skey[j]; ri[r] = sidx[j]; }
    }
    __syncthreads();
    for (int j = tid; j < NP; j += NTT) { skey[j] = -INFINITY; sidx[j] = PAD_IDX; }
    __syncthreads();
    #pragma unroll
    for (int r = 0; r < 2; ++r) {
        int j = tid + r * NTT;
        if (j < cnt) { skey[NP - cnt + j] = rv[r]; sidx[NP - cnt + j] = ri[r]; }
    }
    __syncthreads();

    // ---- sort #1: raw, (val asc, idx desc) -> tail = lax.top_k ----
    if (use_reg) reg_bitonic_256<1>(tid, skey, sidx);
    else         lds_bitonic(tid, skey, sidx, NP, 1);

    // top-T logprobs on raw logits
    if (tid < T) {
        float v = skey[NP - 1 - tid];
        int   ix = sidx[NP - 1 - tid];
        out[B + (size_t)b * T + tid] = __fsub_rn(v, slogS);
        out[B + (size_t)B * T + (size_t)b * T + tid] = (float)ix;
    }
    __syncthreads();

    // ---- transform raw -> processed ----
    const float temp  = temperature[b];
    const float presv = presence[b];
    const float freqv = frequency[b];
    const float repv  = repetition[b];
    const float toppv = top_p[b];
    const int   mint  = min_tokens[b];
    const bool  penalize = olen_l < mint;
    const float teff = (temp < 1e-5f) ? 1.0f : temp;

    for (int j = tid; j < NP; j += NTT) {
        int ix = sidx[j];
        if (ix < V) {
            unsigned info;
            hash_find(hkey, hval, ix, &info);
            skey[j] = process_val(skey[j], info, penalize, repv, freqv, presv, teff);
        }
    }
    __syncthreads();

    // ---- sort #2: processed, (val asc, idx asc) ----
    if (use_reg) reg_bitonic_256<2>(tid, skey, sidx);
    else         lds_bitonic(tid, skey, sidx, NP, 2);

    // ---- parallel precompute of exp / gumbel for top window ----
    int W2 = (NP < PREW) ? NP : PREW;
    int wbase = NP - W2;
    float vmax = skey[NP - 1];
    if (tid < W2) {
        int p = wbase + tid;
        int ix = sidx[p];
        if (ix < V) {
            pre_e[tid] = expf(skey[p] - vmax);
            pre_g[tid] = skey[p] + gumbel_for((uint32_t)b * (uint32_t)V + (uint32_t)ix);
        } else {
            pre_e[tid] = 0.0f;
            pre_g[tid] = -INFINITY;
        }
    }
    __syncthreads();

    // ---- serial epilogue ----
    if (tid == 0) {
        int k = top_k[b];
        if (k < 1) k = 1;
        if (k > V) k = V;
        if (k > cnt) k = cnt;

        float kth = skey[NP - k];
        int p0 = NP - k;
        while (p0 > 0 && skey[p0 - 1] == kth) --p0;

        int q = NP - 1;
        while (q > 0 && skey[q - 1] == vmax) --q;
        int greedy = sidx[q];

        float S2 = 0.0f;
        for (int p = p0; p < NP; ++p) {
            int w = p - wbase;
            S2 += (w >= 0) ? pre_e[w] : expf(skey[p] - vmax);
        }

        float thr = 1.0f - toppv;
        float cum = 0.0f;
        float best = -INFINITY;
        int bestIdx = PAD_IDX;
        for (int p = p0; p < NP; ++p) {
            int w = p - wbase;
            float e = (w >= 0) ? pre_e[w] : expf(skey[p] - vmax);
            cum += e / S2;
            bool drop = (cum <= thr) && (p != NP - 1);
            if (!drop) {
                float score;
                if (w >= 0) score = pre_g[w];
                else {
                    int ix = sidx[p];
                    score = (ix < V) ? skey[p] + gumbel_for((uint32_t)b * (uint32_t)V + (uint32_t)ix)
                                     : -INFINITY;
                }
                if (score > best || (score == best && sidx[p] < bestIdx)) {
                    best = score; bestIdx = sidx[p];
                }
            }
        }
        int sampled = (temp < 1e-5f) ? greedy : bestIdx;
        out[b] = (float)sampled;
    }
}

extern "C" void kernel_launch(void* const* d_in, const int* in_sizes, int n_in,
                              void* d_out, int out_size) {
    const float* logits      = (const float*)d_in[0];
    const float* temperature = (const float*)d_in[1];
    const float* presence    = (const float*)d_in[2];
    const float* frequency   = (const float*)d_in[3];
    const float* repetition  = (const float*)d_in[4];
    const float* topp        = (const float*)d_in[5];
    const int*   prompt      = (const int*)d_in[6];
    const int*   outids      = (const int*)d_in[7];
    const int*   outlens     = (const int*)d_in[8];
    const int*   stops       = (const int*)d_in[9];
    const int*   mintok      = (const int*)d_in[10];
    const int*   topk        = (const int*)d_in[11];

    int B = in_sizes[1];
    int V = in_sizes[0] / B;
    int P = in_sizes[6] / B;
    int O = in_sizes[7] / B;
    int S = in_sizes[9] / B;
    int T = (out_size / B - 1) / 2;

    fused_kernel<<<B, NTT>>>(logits, temperature, presence, frequency, repetition,
                             topp, prompt, outids, outlens, stops, mintok, topk,
                             (float*)d_out, B, V, P, O, S, T);
}